// round 11
// baseline (speedup 1.0000x reference)
#include <cuda_runtime.h>
#include <cstdint>

#define N 256
#define NP 65536u
#define NVOX 16777216u
#define YC 64
#define NSTEPS 70            // 14 * 5; epilogue at t in [4,67]

// ---------------- packed f32x2 helpers (sm_103a) ----------------
union F2U { float2 f; unsigned long long u; };
__device__ __forceinline__ float2 f2add(float2 a, float2 b) {
    F2U x, y, r; x.f = a; y.f = b;
    asm("add.rn.f32x2 %0,%1,%2;" : "=l"(r.u) : "l"(x.u), "l"(y.u));
    return r.f;
}
__device__ __forceinline__ float2 f2mul(float2 a, float2 b) {
    F2U x, y, r; x.f = a; y.f = b;
    asm("mul.rn.f32x2 %0,%1,%2;" : "=l"(r.u) : "l"(x.u), "l"(y.u));
    return r.f;
}
__device__ __forceinline__ float2 f2fma(float2 a, float2 b, float2 c) {
    F2U x, y, zc, r; x.f = a; y.f = b; zc.f = c;
    asm("fma.rn.f32x2 %0,%1,%2,%3;" : "=l"(r.u) : "l"(x.u), "l"(y.u), "l"(zc.u));
    return r.f;
}
__device__ __forceinline__ float2 f2set(float a, float b) { float2 r; r.x = a; r.y = b; return r; }

// ===========================================================================
// Fused NCC forces, 2 voxels/thread, pair-interleaved smem + gradient
// pair-sum register rings. smem per step: 4 STS, 9 LDS. All rings static.
// ===========================================================================
__global__ __launch_bounds__(128, 3) void ncc_fused5_kernel(
    const float* __restrict__ img, const float* __restrict__ ref,
    float* __restrict__ out)
{
    // interleaved rows: arr[x+2] = (a[x], b[x]); pads at idx {0,1,258,259}
    __shared__ __align__(16) float2 q01[2][260];   // (sum_i, sum_r)
    __shared__ __align__(16) float2 q23[2][260];   // (sum_ii, sum_rr)
    __shared__ __align__(16) float  qir_s[2][264]; // sum_ir (scalar row)
    __shared__ __align__(16) float2 ccp[5][260];   // center row ring (img, ref)

    const int t0 = threadIdx.x;       // 0..127
    const int x0 = t0 << 1;
    const int z  = blockIdx.x;
    const int y0 = blockIdx.y * YC;

    // zero pads once
    {
        int pi = t0 & 3;
        int pidx = (pi < 2) ? pi : (pi + 256);
        if (t0 < 8)        q01[t0 >> 2][pidx] = f2set(0.f, 0.f);
        else if (t0 < 16)  q23[(t0 >> 2) & 1][pidx] = f2set(0.f, 0.f);
        else if (t0 < 36)  ccp[(t0 - 16) >> 2][pidx] = f2set(0.f, 0.f);
        else if (t0 < 44)  qir_s[(t0 - 36) >> 2][pidx] = 0.f;
    }

    bool pz[5]; unsigned pb[5];
#pragma unroll
    for (int p = 0; p < 5; p++) {
        int zz = z - 2 + p;
        pz[p] = (zz >= 0) && (zz < N);
        pb[p] = (unsigned)(pz[p] ? zz : 0) * NP + (unsigned)x0;
    }

    const float2 zero2 = f2set(0.f, 0.f);
    const float2 km1   = f2set(-1.f, -1.f);
    const float2 km2   = f2set(-2.f, -2.f);
    const float2 k05   = f2set(0.5f, 0.5f);
    const float2 k025  = f2set(0.25f, 0.25f);
    const float2 k2    = f2set(2.f, 2.f);
    const float2 k125  = f2set(125.f, 125.f);
    const float2 kinv  = f2set(1.f / 125.f, 1.f / 125.f);
    const float2 keps  = f2set(1e-6f, 1e-6f);

    // statically indexed rings (slot = unroll phase j)
    float2 ring[5][5];    // x-boxed quantities (y-box window)
    float2 ez[5];         // encoded z-gradient pair sums
    float2 sc[5];         // center pair sums v2+r2 (y-gradient)
#pragma unroll
    for (int k = 0; k < 5; k++) {
        ez[k] = zero2; sc[k] = zero2;
#pragma unroll
        for (int q = 0; q < 5; q++) ring[q][k] = zero2;
    }

    const bool z_lo = (z == 0);
    const bool z_hi = (z == N - 1);

    // prefetch row t=0 (yl = y0-2)
    float2 pvi[5], pvr[5];
    {
        int yl = y0 - 2;
        bool inr = (yl >= 0);
        unsigned ro = (unsigned)(inr ? yl : 0) * N;
#pragma unroll
        for (int p = 0; p < 5; p++) {
            bool ok = inr && pz[p];
            pvi[p] = ok ? __ldg((const float2*)(img + pb[p] + ro)) : zero2;
            pvr[p] = ok ? __ldg((const float2*)(ref + pb[p] + ro)) : zero2;
        }
    }
    __syncthreads();   // pads + first stores ordering

    int buf = 0;
    for (int tb = 0; tb < 14; ++tb) {
#pragma unroll
        for (int j = 0; j < 5; ++j) {
            const int t = tb * 5 + j;

            // ---- z-summed quantities (packed) ----
            const float2 v0 = pvi[0], v1 = pvi[1], v2 = pvi[2], v3 = pvi[3], v4 = pvi[4];
            const float2 r0 = pvr[0], r1 = pvr[1], r2 = pvr[2], r3 = pvr[3], r4 = pvr[4];
            const float2 qi   = f2add(f2add(f2add(v0, v1), f2add(v2, v3)), v4);
            const float2 qr   = f2add(f2add(f2add(r0, r1), f2add(r2, r3)), r4);
            const float2 qii  = f2fma(v4, v4, f2fma(v3, v3, f2fma(v2, v2, f2fma(v1, v1, f2mul(v0, v0)))));
            const float2 qrr  = f2fma(r4, r4, f2fma(r3, r3, f2fma(r2, r2, f2fma(r1, r1, f2mul(r0, r0)))));
            const float2 qirv = f2fma(v4, r4, f2fma(v3, r3, f2fma(v2, r2, f2fma(v1, r1, f2mul(v0, r0)))));

            // ---- gradient pair-sum rings (no smem needed) ----
            const float2 s_cc = f2add(v2, r2);
            const float2 s_zp = f2add(v3, r3);
            const float2 s_zm = f2add(v1, r1);
            float2 ezv;
            if (z_lo)      ezv = f2mul(f2fma(s_cc, km1, s_zp), k2);
            else if (z_hi) ezv = f2mul(f2fma(s_zm, km1, s_cc), k2);
            else           ezv = f2fma(s_zm, km1, s_zp);
            ez[j] = ezv;
            sc[j] = s_cc;

            // ---- interleaved smem stores ----
            *(float4*)&q01[buf][x0 + 2] = make_float4(qi.x, qr.x, qi.y, qr.y);
            *(float4*)&q23[buf][x0 + 2] = make_float4(qii.x, qrr.x, qii.y, qrr.y);
            *(float2*)&qir_s[buf][x0 + 2] = qirv;
            *(float4*)&ccp[j][x0 + 2] = make_float4(v2.x, r2.x, v2.y, r2.y);

            // ---- prefetch next row ----
            if (t + 1 < NSTEPS) {
                int yn = y0 - 1 + t;
                bool inr = (yn >= 0) && (yn < N);
                unsigned ro = (unsigned)(inr ? yn : 0) * N;
#pragma unroll
                for (int p = 0; p < 5; p++) {
                    bool ok = inr && pz[p];
                    pvi[p] = ok ? __ldg((const float2*)(img + pb[p] + ro)) : zero2;
                    pvr[p] = ok ? __ldg((const float2*)(ref + pb[p] + ro)) : zero2;
                }
            }
            __syncthreads();

            // ---- x-box (own values in regs, paired neighbor loads) ----
            {
                float4 L = *(const float4*)&q01[buf][x0];       // x0-2, x0-1
                float4 R = *(const float4*)&q01[buf][x0 + 4];   // x0+2, x0+3
                float si = L.z + qi.x + qi.y + R.x;
                ring[0][j] = f2set(si + L.x, si + R.z);
                float sr = L.w + qr.x + qr.y + R.y;
                ring[1][j] = f2set(sr + L.y, sr + R.w);
            }
            {
                float4 L = *(const float4*)&q23[buf][x0];
                float4 R = *(const float4*)&q23[buf][x0 + 4];
                float sii = L.z + qii.x + qii.y + R.x;
                ring[2][j] = f2set(sii + L.x, sii + R.z);
                float srr = L.w + qrr.x + qrr.y + R.y;
                ring[3][j] = f2set(srr + L.y, srr + R.w);
            }
            {
                float2 L = *(const float2*)&qir_s[buf][x0];
                float2 R = *(const float2*)&qir_s[buf][x0 + 4];
                float s = L.y + qirv.x + qirv.y + R.x;
                ring[4][j] = f2set(s + L.x, s + R.y);
            }
            buf ^= 1;

            // ---- epilogue for y = y0 + t - 4 ----
            if (t >= 4 && t < 68) {
                const int y = y0 + t - 4;
                const int jc = (j + 3) % 5;   // row y
                const int jp = (j + 4) % 5;   // row y+1
                const int jm = (j + 2) % 5;   // row y-1

                const float2 sum_i  = f2add(f2add(f2add(ring[0][0], ring[0][1]), f2add(ring[0][2], ring[0][3])), ring[0][4]);
                const float2 sum_r  = f2add(f2add(f2add(ring[1][0], ring[1][1]), f2add(ring[1][2], ring[1][3])), ring[1][4]);
                const float2 sum_ii = f2add(f2add(f2add(ring[2][0], ring[2][1]), f2add(ring[2][2], ring[2][3])), ring[2][4]);
                const float2 sum_rr = f2add(f2add(f2add(ring[3][0], ring[3][1]), f2add(ring[3][2], ring[3][3])), ring[3][4]);
                const float2 sum_ir = f2add(f2add(f2add(ring[4][0], ring[4][1]), f2add(ring[4][2], ring[4][3])), ring[4][4]);

                const float2 mi = f2mul(sum_i, kinv);   // faithful: ref mean uses sum_i
                const float2 t1 = f2mul(mi, k125);
                const float2 varr = f2fma(mi, f2fma(sum_r, km2, t1), sum_rr);
                const float2 vari = f2fma(mi, f2fma(sum_i, km2, t1), sum_ii);
                const float2 cross = f2fma(mi, f2fma(f2add(sum_i, sum_r), km1, t1), sum_ir);

                // center row (paired) reads
                const float4 C  = *(const float4*)&ccp[jc][x0 + 2];  // (I,R) at x0, x0+1
                const float2 P  = ccp[jc][x0 + 1];                   // (I,R) at x0-1
                const float2 Nx = ccp[jc][x0 + 4];                   // (I,R) at x0+2
                const float2 ciI = f2set(C.x, C.z);
                const float2 ciR = f2set(C.y, C.w);

                // x gradient: gw = 0.25 * ((I+R)@x+1 - (I+R)@x-1), edge overrides
                const float2 xsl = f2set(P.x + P.y, C.x + C.y);
                const float2 xsr = f2set(C.z + C.w, Nx.x + Nx.y);
                float2 gw = f2mul(f2fma(xsl, km1, xsr), k025);
                const float ge = 0.5f * ((C.z - C.x) + (C.w - C.y));
                if (t0 == 0)   gw.x = ge;
                if (t0 == 127) gw.y = ge;

                // y gradient from sc ring
                float2 gh;
                if (y == 0)          gh = f2mul(f2fma(sc[jc], km1, sc[jp]), k05);
                else if (y == N - 1) gh = f2mul(f2fma(sc[jm], km1, sc[jc]), k05);
                else                 gh = f2mul(f2fma(sc[jm], km1, sc[jp]), k025);

                // z gradient (edge factor pre-encoded in ez)
                const float2 gd = f2mul(ez[jc], k025);

                const float2 den = f2fma(vari, varr, keps);
                float2 rden, cv;
                rden.x = __fdividef(1.f, den.x);
                rden.y = __fdividef(1.f, den.y);
                cv.x = __fdividef(cross.x, varr.x);
                cv.y = __fdividef(cross.y, varr.y);
                const float2 inner = f2fma(f2mul(cv, km1), ciR, ciI);
                const float2 fac = f2mul(f2mul(k2, cross), f2mul(rden, inner));
                const float2 nfac = f2mul(fac, km1);

                const unsigned idx = (unsigned)z * NP + (unsigned)y * N + (unsigned)x0;
                *(float2*)(out + idx)             = f2mul(nfac, gd);
                *(float2*)(out + NVOX + idx)      = f2mul(nfac, gh);
                *(float2*)(out + 2u * NVOX + idx) = f2mul(nfac, gw);
            }
        }
    }
}

// ---------------------------------------------------------------------------
extern "C" void kernel_launch(void* const* d_in, const int* in_sizes, int n_in,
                              void* d_out, int out_size)
{
    const float* img = (const float*)d_in[0];   // image
    const float* ref = (const float*)d_in[2];   // reference_image
    float* out = (float*)d_out;

    dim3 block(128, 1, 1);
    dim3 grid(N, N / YC, 1);    // 256 z x 4 y-chunks
    ncc_fused5_kernel<<<grid, block>>>(img, ref, out);
}

// round 12
// speedup vs baseline: 1.2544x; 1.2544x over previous
#include <cuda_runtime.h>
#include <cstdint>

#define N 256
#define NP 65536u
#define NVOX 16777216u
#define YC 64
#define NSTEPS 70            // 14 * 5; epilogue at t in [4,67]

// ---------------- packed f32x2 helpers (sm_103a) ----------------
union F2U { float2 f; unsigned long long u; };
__device__ __forceinline__ float2 f2add(float2 a, float2 b) {
    F2U x, y, r; x.f = a; y.f = b;
    asm("add.rn.f32x2 %0,%1,%2;" : "=l"(r.u) : "l"(x.u), "l"(y.u));
    return r.f;
}
__device__ __forceinline__ float2 f2mul(float2 a, float2 b) {
    F2U x, y, r; x.f = a; y.f = b;
    asm("mul.rn.f32x2 %0,%1,%2;" : "=l"(r.u) : "l"(x.u), "l"(y.u));
    return r.f;
}
__device__ __forceinline__ float2 f2fma(float2 a, float2 b, float2 c) {
    F2U x, y, zc, r; x.f = a; y.f = b; zc.f = c;
    asm("fma.rn.f32x2 %0,%1,%2,%3;" : "=l"(r.u) : "l"(x.u), "l"(y.u), "l"(zc.u));
    return r.f;
}
__device__ __forceinline__ float2 f2set(float a, float b) { float2 r; r.x = a; r.y = b; return r; }

// ===========================================================================
// Fused NCC forces, 2 voxels/thread, pair-interleaved smem, static rings,
// register budget <=128 for 4 CTAs/SM.
// ===========================================================================
__global__ __launch_bounds__(128, 4) void ncc_fused6_kernel(
    const float* __restrict__ img, const float* __restrict__ ref,
    float* __restrict__ out)
{
    __shared__ __align__(16) float2 q01[2][260];   // (sum_i, sum_r) interleaved
    __shared__ __align__(16) float2 q23[2][260];   // (sum_ii, sum_rr) interleaved
    __shared__ __align__(16) float  qir_s[2][264]; // sum_ir scalar row
    __shared__ __align__(16) float2 ccp[5][260];   // center row ring (img, ref)

    const int t0 = threadIdx.x;       // 0..127
    const int x0 = t0 << 1;
    const int z  = blockIdx.x;
    const int y0 = blockIdx.y * YC;

    // zero pads once
    {
        int pi = t0 & 3;
        int pidx = (pi < 2) ? pi : (pi + 256);
        if (t0 < 8)        q01[t0 >> 2][pidx] = f2set(0.f, 0.f);
        else if (t0 < 16)  q23[(t0 >> 2) & 1][pidx] = f2set(0.f, 0.f);
        else if (t0 < 36)  ccp[(t0 - 16) >> 2][pidx] = f2set(0.f, 0.f);
        else if (t0 < 44)  qir_s[(t0 - 36) >> 2][pidx] = 0.f;
    }

    bool pz[5]; unsigned pb[5];
#pragma unroll
    for (int p = 0; p < 5; p++) {
        int zz = z - 2 + p;
        pz[p] = (zz >= 0) && (zz < N);
        pb[p] = (unsigned)(pz[p] ? zz : 0) * NP + (unsigned)x0;
    }

    const float2 zero2 = f2set(0.f, 0.f);
    const float2 km1   = f2set(-1.f, -1.f);
    const float2 km2   = f2set(-2.f, -2.f);
    const float2 kn2   = f2set(-2.f, -2.f);   // alias ok; ptxas will CSE
    const float2 k05   = f2set(0.5f, 0.5f);
    const float2 k025  = f2set(0.25f, 0.25f);
    const float2 k2    = f2set(2.f, 2.f);
    const float2 kinv  = f2set(1.f / 125.f, 1.f / 125.f);
    const float2 keps  = f2set(1e-6f, 1e-6f);

    // statically indexed rings (slot = unroll phase j)
    float2 ring[5][5];    // x-boxed quantities (y-box window)
    float2 ez[5];         // encoded z-gradient pair sums
    float2 sc[5];         // center pair sums v2+r2 (y-gradient)
#pragma unroll
    for (int k = 0; k < 5; k++) {
        ez[k] = zero2; sc[k] = zero2;
#pragma unroll
        for (int q = 0; q < 5; q++) ring[q][k] = zero2;
    }

    const bool z_lo = (z == 0);
    const bool z_hi = (z == N - 1);

    // prefetch row t=0 (yl = y0-2)
    float2 pvi[5], pvr[5];
    {
        int yl = y0 - 2;
        bool inr = (yl >= 0);
        unsigned ro = (unsigned)(inr ? yl : 0) * N;
#pragma unroll
        for (int p = 0; p < 5; p++) {
            bool ok = inr && pz[p];
            pvi[p] = ok ? __ldg((const float2*)(img + pb[p] + ro)) : zero2;
            pvr[p] = ok ? __ldg((const float2*)(ref + pb[p] + ro)) : zero2;
        }
    }
    __syncthreads();

    int buf = 0;
    for (int tb = 0; tb < 14; ++tb) {
#pragma unroll
        for (int j = 0; j < 5; ++j) {
            const int t = tb * 5 + j;

            // ---- z-summed quantities (packed) ----
            const float2 v0 = pvi[0], v1 = pvi[1], v2 = pvi[2], v3 = pvi[3], v4 = pvi[4];
            const float2 r0 = pvr[0], r1 = pvr[1], r2 = pvr[2], r3 = pvr[3], r4 = pvr[4];
            const float2 qi   = f2add(f2add(f2add(v0, v1), f2add(v2, v3)), v4);
            const float2 qr   = f2add(f2add(f2add(r0, r1), f2add(r2, r3)), r4);
            const float2 qii  = f2fma(v4, v4, f2fma(v3, v3, f2fma(v2, v2, f2fma(v1, v1, f2mul(v0, v0)))));
            const float2 qrr  = f2fma(r4, r4, f2fma(r3, r3, f2fma(r2, r2, f2fma(r1, r1, f2mul(r0, r0)))));
            const float2 qirv = f2fma(v4, r4, f2fma(v3, r3, f2fma(v2, r2, f2fma(v1, r1, f2mul(v0, r0)))));

            // ---- gradient pair-sum rings ----
            const float2 s_cc = f2add(v2, r2);
            const float2 s_zp = f2add(v3, r3);
            const float2 s_zm = f2add(v1, r1);
            float2 ezv;
            if (z_lo)      ezv = f2mul(f2fma(s_cc, km1, s_zp), k2);
            else if (z_hi) ezv = f2mul(f2fma(s_zm, km1, s_cc), k2);
            else           ezv = f2fma(s_zm, km1, s_zp);
            ez[j] = ezv;
            sc[j] = s_cc;

            // ---- interleaved smem stores ----
            *(float4*)&q01[buf][x0 + 2] = make_float4(qi.x, qr.x, qi.y, qr.y);
            *(float4*)&q23[buf][x0 + 2] = make_float4(qii.x, qrr.x, qii.y, qrr.y);
            *(float2*)&qir_s[buf][x0 + 2] = qirv;
            *(float4*)&ccp[j][x0 + 2] = make_float4(v2.x, r2.x, v2.y, r2.y);

            // ---- prefetch next row ----
            if (t + 1 < NSTEPS) {
                int yn = y0 - 1 + t;
                bool inr = (yn >= 0) && (yn < N);
                unsigned ro = (unsigned)(inr ? yn : 0) * N;
#pragma unroll
                for (int p = 0; p < 5; p++) {
                    bool ok = inr && pz[p];
                    pvi[p] = ok ? __ldg((const float2*)(img + pb[p] + ro)) : zero2;
                    pvr[p] = ok ? __ldg((const float2*)(ref + pb[p] + ro)) : zero2;
                }
            }
            __syncthreads();

            // ---- x-box (own values in regs, paired neighbor loads) ----
            {
                float4 L = *(const float4*)&q01[buf][x0];
                float4 R = *(const float4*)&q01[buf][x0 + 4];
                float si = L.z + qi.x + qi.y + R.x;
                ring[0][j] = f2set(si + L.x, si + R.z);
                float sr = L.w + qr.x + qr.y + R.y;
                ring[1][j] = f2set(sr + L.y, sr + R.w);
            }
            {
                float4 L = *(const float4*)&q23[buf][x0];
                float4 R = *(const float4*)&q23[buf][x0 + 4];
                float sii = L.z + qii.x + qii.y + R.x;
                ring[2][j] = f2set(sii + L.x, sii + R.z);
                float srr = L.w + qrr.x + qrr.y + R.y;
                ring[3][j] = f2set(srr + L.y, srr + R.w);
            }
            {
                float2 L = *(const float2*)&qir_s[buf][x0];
                float2 R = *(const float2*)&qir_s[buf][x0 + 4];
                float s = L.y + qirv.x + qirv.y + R.x;
                ring[4][j] = f2set(s + L.x, s + R.y);
            }
            buf ^= 1;

            // ---- epilogue for y = y0 + t - 4 ----
            if (t >= 4 && t < 68) {
                const int y = y0 + t - 4;
                const int jc = (j + 3) % 5;
                const int jp = (j + 4) % 5;
                const int jm = (j + 2) % 5;

                const float2 sum_i  = f2add(f2add(f2add(ring[0][0], ring[0][1]), f2add(ring[0][2], ring[0][3])), ring[0][4]);
                const float2 sum_r  = f2add(f2add(f2add(ring[1][0], ring[1][1]), f2add(ring[1][2], ring[1][3])), ring[1][4]);
                const float2 sum_ii = f2add(f2add(f2add(ring[2][0], ring[2][1]), f2add(ring[2][2], ring[2][3])), ring[2][4]);
                const float2 sum_rr = f2add(f2add(f2add(ring[3][0], ring[3][1]), f2add(ring[3][2], ring[3][3])), ring[3][4]);
                const float2 sum_ir = f2add(f2add(f2add(ring[4][0], ring[4][1]), f2add(ring[4][2], ring[4][3])), ring[4][4]);

                // mr = mi (faithful); 125*mi folded to sum_i (error ~1e-7 rel)
                const float2 mi = f2mul(sum_i, kinv);
                const float2 nmi = f2mul(mi, km1);
                const float2 varr = f2fma(mi, f2fma(sum_r, km2, sum_i), sum_rr);  // sum_rr + mi*(sum_i - 2 sum_r)
                const float2 vari = f2fma(nmi, sum_i, sum_ii);                    // sum_ii - mi*sum_i
                const float2 cross = f2fma(nmi, sum_r, sum_ir);                   // sum_ir - mi*sum_r

                // center row reads
                const float4 C  = *(const float4*)&ccp[jc][x0 + 2];
                const float2 P  = ccp[jc][x0 + 1];
                const float2 Nx = ccp[jc][x0 + 4];
                const float2 ciI = f2set(C.x, C.z);
                const float2 ciR = f2set(C.y, C.w);

                // x gradient
                const float2 xsl = f2set(P.x + P.y, C.x + C.y);
                const float2 xsr = f2set(C.z + C.w, Nx.x + Nx.y);
                float2 gw = f2mul(f2fma(xsl, km1, xsr), k025);
                const float ge = 0.5f * ((C.z - C.x) + (C.w - C.y));
                if (t0 == 0)   gw.x = ge;
                if (t0 == 127) gw.y = ge;

                // y gradient
                float2 gh;
                if (y == 0)          gh = f2mul(f2fma(sc[jc], km1, sc[jp]), k05);
                else if (y == N - 1) gh = f2mul(f2fma(sc[jm], km1, sc[jc]), k05);
                else                 gh = f2mul(f2fma(sc[jm], km1, sc[jp]), k025);

                // z gradient
                const float2 gd = f2mul(ez[jc], k025);

                const float2 den = f2fma(vari, varr, keps);
                float2 rden, cv;
                rden.x = __fdividef(1.f, den.x);
                rden.y = __fdividef(1.f, den.y);
                cv.x = __fdividef(cross.x, varr.x);
                cv.y = __fdividef(cross.y, varr.y);
                const float2 inner = f2fma(f2mul(cv, km1), ciR, ciI);
                // nfac = -2 * cross * rden * inner
                const float2 nfac = f2mul(f2mul(kn2, cross), f2mul(rden, inner));

                const unsigned idx = (unsigned)z * NP + (unsigned)y * N + (unsigned)x0;
                *(float2*)(out + idx)             = f2mul(nfac, gd);
                *(float2*)(out + NVOX + idx)      = f2mul(nfac, gh);
                *(float2*)(out + 2u * NVOX + idx) = f2mul(nfac, gw);
            }
        }
    }
}

// ---------------------------------------------------------------------------
extern "C" void kernel_launch(void* const* d_in, const int* in_sizes, int n_in,
                              void* d_out, int out_size)
{
    const float* img = (const float*)d_in[0];   // image
    const float* ref = (const float*)d_in[2];   // reference_image
    float* out = (float*)d_out;

    dim3 block(128, 1, 1);
    dim3 grid(N, N / YC, 1);    // 256 z x 4 y-chunks
    ncc_fused6_kernel<<<grid, block>>>(img, ref, out);
}